// round 13
// baseline (speedup 1.0000x reference)
#include <cuda_runtime.h>
#include <cuda_bf16.h>
#include <math.h>
#include <stdint.h>

#define B_ROWS 16384
#define K_DIM  10000
#define FEAT   128
#define PREF   2
#define XDIM   130   // FEAT + PREF
#define NEXP   4
#define ACT    8

#define BK       64
#define KT_TILES 157          // ceil(10000/64)

// tcgen05 is an arch-specific ("a") feature. The harness build includes a plain
// compute_103/sm_103 pass where tcgen05 does not exist — that pass gets the
// proven scalar fallback bodies instead. Host pass: value irrelevant.
#if !defined(__CUDA_ARCH__) || defined(__CUDA_ARCH_FEAT_SM103_ALL) || defined(__CUDA_ARCH_FEAT_SM100_ALL) || defined(__CUDA_ARCH_FEAT_SM110_ALL)
#define HAS_TCGEN05 1
#else
#define HAS_TCGEN05 0
#endif

// ---------------- device scratch (no allocations allowed) ----------------
__device__ float g_xfeat[(size_t)B_ROWS * FEAT];
// pre-swizzled bf16 weight tiles (main GEMM): [KT_TILES][128 n x 64 k] 16B units
__device__ uint4 g_Wsw_hi[KT_TILES * 1024];
__device__ uint4 g_Wsw_lo[KT_TILES * 1024];
// pre-swizzled head weights: 5 matrices (0=critic Wc1, 1..4=experts) x 3 ktiles
__device__ uint4 g_Hsw_hi[5 * 3 * 1024];
__device__ uint4 g_Hsw_lo[5 * 3 * 1024];

// ---------------- generic helpers (valid on every target) ----------------
__device__ __forceinline__ float lrelu(float x) { return x >= 0.0f ? x : 0.01f * x; }

// split f32 pair -> bf16x2 hi + bf16x2 lo  (x0 in low half, x1 in high half)
__device__ __forceinline__ void split2(float x0, float x1, uint32_t& h, uint32_t& l) {
    asm("cvt.rn.bf16x2.f32 %0, %1, %2;" : "=r"(h) : "f"(x1), "f"(x0));
    float hf0 = __uint_as_float(h << 16);
    float hf1 = __uint_as_float(h & 0xFFFF0000u);
    float r0 = x0 - hf0, r1 = x1 - hf1;
    asm("cvt.rn.bf16x2.f32 %0, %1, %2;" : "=r"(l) : "f"(r1), "f"(r0));
}

// ---- packed f32x2 helpers (scalar fallback paths) ----
#define FMA2(acc, a, b) asm("fma.rn.f32x2 %0, %1, %2, %0;" : "+l"(acc) : "l"(a), "l"(b))
__device__ __forceinline__ unsigned long long pack2(float v) {
    unsigned long long r; asm("mov.b64 %0, {%1, %1};" : "=l"(r) : "f"(v)); return r;
}
__device__ __forceinline__ float2 unpack2(unsigned long long v) {
    float2 r; asm("mov.b64 {%0, %1}, %2;" : "=f"(r.x), "=f"(r.y) : "l"(v)); return r;
}

// ============================================================================
// Kernel 0: convert Wf [10000 x 128] f32 -> pre-swizzled bf16 hi/lo K-major
// ============================================================================
__global__ __launch_bounds__(256) void prep_w(const float* __restrict__ Wf) {
    int u = blockIdx.x * 256 + threadIdx.x;
    if (u >= KT_TILES * 1024) return;
    int n   = u & 127;
    int kc8 = (u >> 7) & 7;
    int kt  = u >> 10;
    float v[8];
#pragma unroll
    for (int i = 0; i < 8; i++) {
        int k = kt * BK + kc8 * 8 + i;
        v[i] = (k < K_DIM) ? Wf[(size_t)k * FEAT + n] : 0.0f;
    }
    uint4 H, L;
    split2(v[0], v[1], H.x, L.x);
    split2(v[2], v[3], H.y, L.y);
    split2(v[4], v[5], H.z, L.z);
    split2(v[6], v[7], H.w, L.w);
    uint32_t off = n * 128 + kc8 * 16;
    uint32_t sw  = off ^ ((off >> 3) & 0x70);
    int unit = (int)(sw >> 4);
    g_Wsw_hi[kt * 1024 + unit] = H;
    g_Wsw_lo[kt * 1024 + unit] = L;
}

// ============================================================================
// Kernel 0b: head weights -> swizzled bf16 hi/lo B tiles.
// ============================================================================
__global__ __launch_bounds__(256) void prep_head(
    const float* __restrict__ Wc1, const float* __restrict__ Wa1)
{
    int u = blockIdx.x * 256 + threadIdx.x;
    if (u >= 5 * 3 * 1024) return;
    int m    = u / 3072;
    int rem  = u % 3072;
    int kt   = rem >> 10;
    int id   = rem & 1023;
    int j    = id >> 3;
    int kc8  = id & 7;
    float v[8];
#pragma unroll
    for (int i = 0; i < 8; i++) {
        int k = kt * 64 + kc8 * 8 + i;
        float w = 0.0f;
        if (k < XDIM)
            w = (m == 0) ? Wc1[(size_t)k * FEAT + j]
                         : Wa1[(size_t)((m - 1) * XDIM + k) * FEAT + j];
        v[i] = w;
    }
    uint4 H, L;
    split2(v[0], v[1], H.x, L.x);
    split2(v[2], v[3], H.y, L.y);
    split2(v[4], v[5], H.z, L.z);
    split2(v[6], v[7], H.w, L.w);
    uint32_t off = (uint32_t)j * 128 + kc8 * 16;
    uint32_t sw  = off ^ ((off >> 3) & 0x70);
    int unit = (int)(sw >> 4);
    g_Hsw_hi[(m * 3 + kt) * 1024 + unit] = H;
    g_Hsw_lo[(m * 3 + kt) * 1024 + unit] = L;
}

// ============================================================================
// arch-specific helpers (only compiled into the sm_103a/sm_100a device pass)
// ============================================================================
#if HAS_TCGEN05

__device__ __forceinline__ uint32_t smem_u32(const void* p) {
    uint32_t a;
    asm("{ .reg .u64 t; cvta.to.shared.u64 t, %1; cvt.u32.u64 %0, t; }" : "=r"(a) : "l"(p));
    return a;
}
__device__ __forceinline__ uint32_t elect_one() {
    uint32_t p;
    asm volatile("{ .reg .pred p; elect.sync _|p, 0xFFFFFFFF; selp.b32 %0, 1, 0, p; }" : "=r"(p));
    return p;
}
#define MBAR_INIT(a, c) asm volatile("mbarrier.init.shared.b64 [%0], %1;" :: "r"(a), "r"(c) : "memory")
#define MBAR_WAIT(a, ph) do {                                                          \
    asm volatile("{ .reg .pred P;                                                      \
      WL%=: mbarrier.try_wait.parity.acquire.cta.shared::cta.b64 P, [%0], %1, 0x989680;\
      @P bra.uni WD%=; bra.uni WL%=; WD%=: }" :: "r"(a), "r"(ph) : "memory");          \
} while (0)
#define MBAR_EXPECT_TX(a, n) asm volatile("mbarrier.arrive.expect_tx.shared.b64 _, [%0], %1;" :: "r"(a), "r"(n) : "memory")
#define BULK_G2S(dst, src, n, mbar) asm volatile(                                       \
    "cp.async.bulk.shared::cluster.global.mbarrier::complete_tx::bytes [%0], [%1], %2, [%3];" \
    :: "r"(dst), "l"(src), "r"(n), "r"(mbar) : "memory")
#define TC_ALLOC(sa, n)   asm volatile("tcgen05.alloc.cta_group::1.sync.aligned.shared::cta.b32 [%0], %1;" :: "r"(sa), "r"(n) : "memory")
#define TC_DEALLOC(t, n)  asm volatile("tcgen05.dealloc.cta_group::1.sync.aligned.b32 %0, %1;" :: "r"(t), "r"(n))
#define TC_RELINQ()       asm volatile("tcgen05.relinquish_alloc_permit.cta_group::1.sync.aligned;")
#define TC_COMMIT(a)      asm volatile("tcgen05.commit.cta_group::1.mbarrier::arrive::one.shared::cluster.b64 [%0];" :: "r"(a) : "memory")
#define TC_WAIT_LD()      asm volatile("tcgen05.wait::ld.sync.aligned;" ::: "memory")
#define TC_FENCE_AFTER()  asm volatile("tcgen05.fence::after_thread_sync;" ::: "memory")
#define TC_FENCE_BEFORE() asm volatile("tcgen05.fence::before_thread_sync;" ::: "memory")
#define FENCE_ASYNC()     asm volatile("fence.proxy.async.shared::cta;" ::: "memory")

#define LDTM_X32(r, a) asm volatile(                                            \
    "tcgen05.ld.sync.aligned.32x32b.x32.b32 "                                   \
    "{%0,%1,%2,%3,%4,%5,%6,%7,%8,%9,%10,%11,%12,%13,%14,%15,"                   \
    "%16,%17,%18,%19,%20,%21,%22,%23,%24,%25,%26,%27,%28,%29,%30,%31}, [%32];"  \
    : "=r"((r)[0]),"=r"((r)[1]),"=r"((r)[2]),"=r"((r)[3]),                      \
      "=r"((r)[4]),"=r"((r)[5]),"=r"((r)[6]),"=r"((r)[7]),                      \
      "=r"((r)[8]),"=r"((r)[9]),"=r"((r)[10]),"=r"((r)[11]),                    \
      "=r"((r)[12]),"=r"((r)[13]),"=r"((r)[14]),"=r"((r)[15]),                  \
      "=r"((r)[16]),"=r"((r)[17]),"=r"((r)[18]),"=r"((r)[19]),                  \
      "=r"((r)[20]),"=r"((r)[21]),"=r"((r)[22]),"=r"((r)[23]),                  \
      "=r"((r)[24]),"=r"((r)[25]),"=r"((r)[26]),"=r"((r)[27]),                  \
      "=r"((r)[28]),"=r"((r)[29]),"=r"((r)[30]),"=r"((r)[31])                   \
    : "r"(a))

__device__ __forceinline__ uint64_t make_desc(uint32_t addr) {
    const uint64_t BASE = (2ull << 61) | (1ull << 46) | (64ull << 32) | (1ull << 16); // SW128, ver1, SBO=64, LBO=1
    return BASE | ((uint64_t)(addr >> 4) & 0x3FFF);
}

// idesc kind::f16: dtype=F32, a/b=BF16, N=128, M=128
#define MMA_IDESC ((1u << 4) | (1u << 7) | (1u << 10) | (16u << 17) | (8u << 24))

__device__ __forceinline__ void mma_f16_ss(uint32_t d, uint64_t ad, uint64_t bd, uint32_t en) {
    asm volatile(
        "{\n\t.reg .pred p;\n\tsetp.ne.u32 p, %5, 0;\n\t"
        "tcgen05.mma.cta_group::1.kind::f16 [%0], %1, %2, %3, {%4, %4, %4, %4}, p;\n\t}"
        :: "r"(d), "l"(ad), "l"(bd), "r"(MMA_IDESC), "r"(0u), "r"(en) : "memory");
}

#endif // HAS_TCGEN05

// ============================================================================
// Kernel A: x = leaky_relu(obs @ Wf + bf)
//  sm_103a: tcgen05 split-bf16, 3-stage ring, B via cp.async.bulk
// smem: [0..4) tmem ptr | 16,24,32 mbarM[3] | 40,48,56 mbarF[3] | tiles @1024
// ============================================================================
#define TILE_OFF(s, b) (1024u + (((uint32_t)(s) * 4u) + (b)) * 16384u)  // 0=Ah 1=Al 2=Bh 3=Bl
#define GEMM_SMEM (1024 + 12 * 16384)

__global__ __launch_bounds__(256) void feat_gemm_tc(
    const float* __restrict__ A,     // obs [B_ROWS, K_DIM]
    const float* __restrict__ W,     // Wf (fallback path only)
    const float* __restrict__ bias)  // bf [FEAT]
{
#if HAS_TCGEN05
    extern __shared__ char smem[];
    const uint32_t sb  = smem_u32(smem);
    const int tid = threadIdx.x;
    const int wid = tid >> 5, lid = tid & 31;
    const int m0  = blockIdx.x * 128;

    if (wid == 0) TC_ALLOC(sb, 128);
    if (tid == 0) {
#pragma unroll
        for (int s = 0; s < 3; s++) { MBAR_INIT(sb + 16 + 8 * s, 1); MBAR_INIT(sb + 40 + 8 * s, 1); }
    }
    __syncthreads();
    uint32_t tmem;
    asm volatile("ld.shared.b32 %0, [%1];" : "=r"(tmem) : "r"(sb));

    float4 areg[8];
    const float4 z4 = make_float4(0.f, 0.f, 0.f, 0.f);

    int rowv[4], col8v[4];
#pragma unroll
    for (int j = 0; j < 4; j++) { int oc = j * 256 + tid; rowv[j] = oc >> 3; col8v[j] = oc & 7; }

#define LOAD_A(kt)                                                                  \
    do {                                                                            \
        _Pragma("unroll")                                                           \
        for (int j = 0; j < 4; j++) {                                               \
            int k = (kt) * BK + col8v[j] * 8;                                       \
            const float* bp = A + (size_t)(m0 + rowv[j]) * K_DIM + k;               \
            areg[2 * j]     = (k + 3 < K_DIM) ? *(const float4*)(bp)     : z4;      \
            areg[2 * j + 1] = (k + 7 < K_DIM) ? *(const float4*)(bp + 4) : z4;      \
        }                                                                           \
    } while (0)

#define STORE_A(s)                                                                  \
    do {                                                                            \
        uint32_t ah_b = sb + TILE_OFF(s, 0), al_b = sb + TILE_OFF(s, 1);            \
        _Pragma("unroll")                                                           \
        for (int j = 0; j < 4; j++) {                                               \
            uint32_t off = rowv[j] * 128 + col8v[j] * 16;                           \
            uint32_t sw  = off ^ ((off >> 3) & 0x70);                               \
            uint4 H, L;                                                             \
            split2(areg[2 * j].x,     areg[2 * j].y,     H.x, L.x);                 \
            split2(areg[2 * j].z,     areg[2 * j].w,     H.y, L.y);                 \
            split2(areg[2 * j + 1].x, areg[2 * j + 1].y, H.z, L.z);                 \
            split2(areg[2 * j + 1].z, areg[2 * j + 1].w, H.w, L.w);                 \
            asm volatile("st.shared.v4.b32 [%0], {%1,%2,%3,%4};"                    \
                :: "r"(ah_b + sw), "r"(H.x), "r"(H.y), "r"(H.z), "r"(H.w) : "memory"); \
            asm volatile("st.shared.v4.b32 [%0], {%1,%2,%3,%4};"                    \
                :: "r"(al_b + sw), "r"(L.x), "r"(L.y), "r"(L.z), "r"(L.w) : "memory"); \
        }                                                                           \
    } while (0)

#define ISSUE_STAGE(s, first)                                                       \
    do {                                                                            \
        uint64_t ahd = make_desc(sb + TILE_OFF(s, 0));                              \
        uint64_t ald = make_desc(sb + TILE_OFF(s, 1));                              \
        uint64_t bhd = make_desc(sb + TILE_OFF(s, 2));                              \
        uint64_t bld = make_desc(sb + TILE_OFF(s, 3));                              \
        uint32_t en = (first) ? 0u : 1u;                                            \
        _Pragma("unroll")                                                           \
        for (int kc = 0; kc < 4; kc++) {                                            \
            mma_f16_ss(tmem, ahd + 2 * kc, bhd + 2 * kc, en); en = 1u;              \
            mma_f16_ss(tmem, ahd + 2 * kc, bld + 2 * kc, 1u);                       \
            mma_f16_ss(tmem, ald + 2 * kc, bhd + 2 * kc, 1u);                       \
        }                                                                           \
    } while (0)

    LOAD_A(0);

#pragma unroll 1
    for (int kt = 0; kt < KT_TILES; kt++) {
        const int s = kt % 3, c = kt / 3;
        const uint32_t mbM = sb + 16 + 8u * s;
        const uint32_t mbF = sb + 40 + 8u * s;
        if (kt >= 3) { MBAR_WAIT(mbM, (c - 1) & 1); TC_FENCE_AFTER(); }
        if (wid == 0 && elect_one()) {
            MBAR_EXPECT_TX(mbF, 32768u);
            BULK_G2S(sb + TILE_OFF(s, 2), (const char*)g_Wsw_hi + (size_t)kt * 16384, 16384u, mbF);
            BULK_G2S(sb + TILE_OFF(s, 3), (const char*)g_Wsw_lo + (size_t)kt * 16384, 16384u, mbF);
        }
        STORE_A(s);
        if (kt + 1 < KT_TILES) LOAD_A(kt + 1);
        __syncthreads();
        if (wid == 0 && elect_one()) {
            FENCE_ASYNC();
            TC_FENCE_AFTER();
            MBAR_WAIT(mbF, c & 1);
            ISSUE_STAGE(s, kt == 0);
            TC_COMMIT(mbM);
        }
    }

    // last commit (kt=156) went to mbarM[0]; its pending phase has parity 0
    MBAR_WAIT(sb + 16, 0);
    TC_FENCE_AFTER();

    {
        const int sub = wid & 3;
        const int mrow = m0 + sub * 32 + lid;
        const int cb = (wid >> 2) * 64;
        float* orow = g_xfeat + (size_t)mrow * FEAT + cb;
#pragma unroll
        for (int half = 0; half < 2; half++) {
            uint32_t r[32];
            LDTM_X32(r, tmem + cb + half * 32);
            TC_WAIT_LD();
#pragma unroll
            for (int q = 0; q < 8; q++) {
                float4 bq = *(const float4*)(bias + cb + half * 32 + q * 4);
                float4 o;
                o.x = lrelu(__uint_as_float(r[q * 4 + 0]) + bq.x);
                o.y = lrelu(__uint_as_float(r[q * 4 + 1]) + bq.y);
                o.z = lrelu(__uint_as_float(r[q * 4 + 2]) + bq.z);
                o.w = lrelu(__uint_as_float(r[q * 4 + 3]) + bq.w);
                *(float4*)(orow + half * 32 + q * 4) = o;
            }
        }
    }
    TC_FENCE_BEFORE();
    __syncthreads();
    if (wid == 0) { TC_RELINQ(); TC_DEALLOC(tmem, 128); }

#else
    // ---------------- fallback: proven scalar f32x2 GEMM ----------------
    __shared__ float As[32][132];
    __shared__ float Bs[32][128];

    const int tid = threadIdx.x;
    const int tx = tid & 15;
    const int ty = tid >> 4;
    const int m0 = blockIdx.x * 128;

    unsigned long long acc[8][4];
#pragma unroll
    for (int i = 0; i < 8; i++)
#pragma unroll
        for (int j = 0; j < 4; j++) acc[i][j] = 0ULL;

    const float4 z4 = make_float4(0.f, 0.f, 0.f, 0.f);
    float4 aReg[4], bReg[4];
    const int KT = (K_DIM + 31) / 32;

    {
        const int k0 = 0;
#pragma unroll
        for (int j = 0; j < 4; j++) {
            int c = tid + 256 * j;
            int row = c >> 3, kq = c & 7;
            int k = k0 + kq * 4;
            aReg[j] = (k < K_DIM)
                ? *(const float4*)(A + (size_t)(m0 + row) * K_DIM + k) : z4;
        }
#pragma unroll
        for (int j = 0; j < 4; j++) {
            int c = tid + 256 * j;
            int kr = c >> 5, nq = c & 31;
            int k = k0 + kr;
            bReg[j] = (k < K_DIM)
                ? *(const float4*)(W + (size_t)k * FEAT + nq * 4) : z4;
        }
    }

#pragma unroll 1
    for (int kt = 0; kt < KT; kt++) {
        __syncthreads();
#pragma unroll
        for (int j = 0; j < 4; j++) {
            int c = tid + 256 * j;
            int row = c >> 3, kq = c & 7;
            As[kq * 4 + 0][row] = aReg[j].x;
            As[kq * 4 + 1][row] = aReg[j].y;
            As[kq * 4 + 2][row] = aReg[j].z;
            As[kq * 4 + 3][row] = aReg[j].w;
        }
#pragma unroll
        for (int j = 0; j < 4; j++) {
            int c = tid + 256 * j;
            int kr = c >> 5, nq = c & 31;
            *(float4*)&Bs[kr][nq * 4] = bReg[j];
        }
        __syncthreads();

        if (kt + 1 < KT) {
            const int k0 = (kt + 1) * 32;
#pragma unroll
            for (int j = 0; j < 4; j++) {
                int c = tid + 256 * j;
                int row = c >> 3, kq = c & 7;
                int k = k0 + kq * 4;
                aReg[j] = (k < K_DIM)
                    ? *(const float4*)(A + (size_t)(m0 + row) * K_DIM + k) : z4;
            }
#pragma unroll
            for (int j = 0; j < 4; j++) {
                int c = tid + 256 * j;
                int kr = c >> 5, nq = c & 31;
                int k = k0 + kr;
                bReg[j] = (k < K_DIM)
                    ? *(const float4*)(W + (size_t)k * FEAT + nq * 4) : z4;
            }
        }

#pragma unroll 8
        for (int k = 0; k < 32; k++) {
            float4 a0 = *(const float4*)&As[k][ty * 8];
            float4 a1 = *(const float4*)&As[k][ty * 8 + 4];
            ulonglong2 b0 = *(const ulonglong2*)&Bs[k][tx * 8];
            ulonglong2 b1 = *(const ulonglong2*)&Bs[k][tx * 8 + 4];
            float av[8] = {a0.x, a0.y, a0.z, a0.w, a1.x, a1.y, a1.z, a1.w};
#pragma unroll
            for (int im = 0; im < 8; im++) {
                unsigned long long a2 = pack2(av[im]);
                FMA2(acc[im][0], a2, b0.x);
                FMA2(acc[im][1], a2, b0.y);
                FMA2(acc[im][2], a2, b1.x);
                FMA2(acc[im][3], a2, b1.y);
            }
        }
    }

    const int n0 = tx * 8;
#pragma unroll
    for (int im = 0; im < 8; im++) {
        size_t m = (size_t)m0 + ty * 8 + im;
#pragma unroll
        for (int jp = 0; jp < 4; jp++) {
            float2 v = unpack2(acc[im][jp]);
            int n = n0 + jp * 2;
            v.x = lrelu(v.x + bias[n]);
            v.y = lrelu(v.y + bias[n + 1]);
            *(float2*)&g_xfeat[m * FEAT + n] = v;
        }
    }
#endif // HAS_TCGEN05
}

// ============================================================================
// Kernel B: routing + MoE actor + critic.
//  sm_103a: tcgen05 MMA, B via cp.async.bulk, epilogues interleaved with MMAs.
// smem (tc path) — FIXED layout (R11 overlapped polbuf with valbuf/wa2s):
//  0 tmem ptr | 16 mbar0 | 24 mbar1 | 32 mbarBF | 64 idxs[128] | 576 bc1s[128]
//  1088 ba1s[4][128] | 3136 ba2s[4][8] | 3264 bc2s[2] | 3328 wc2s[256]
//  4352 polbuf[128][2][8] (8192B) | 12544 valbuf[128][2][2] (2048B)
//  14592 wa2s[4096] (16384B, ends 30976)
//  32768 A tiles (3kt x hi/lo x 16KB) | 131072 B hi (3x16KB) | 180224 B lo (3x16KB)
// ============================================================================
#define HA_OFF(kt, h) (32768u  + ((uint32_t)(kt) * 2u + (h)) * 16384u)
#define HB_HI(kt)     (131072u + (uint32_t)(kt) * 16384u)
#define HB_LO(kt)     (180224u + (uint32_t)(kt) * 16384u)
#define HEAD_SMEM 229376

struct SmemB {
    float xs[128][133];
    float wbuf[XDIM * FEAT];
    float wa2s[NEXP * FEAT * ACT];
    float wc2s[FEAT * 2];
    float polbuf[128][2][ACT];
    float valbuf[128][2][2];
    float bc1s[FEAT];
    float ba1s[NEXP][FEAT];
    float ba2s[NEXP][ACT];
    float bc2s[2];
    int   idxs[128];
};

__global__ __launch_bounds__(256) void head_net(
    const float* __restrict__ pref,
    const float* __restrict__ Wa1, const float* __restrict__ ba1,
    const float* __restrict__ Wa2, const float* __restrict__ ba2,
    const float* __restrict__ Wc1, const float* __restrict__ bc1,
    const float* __restrict__ Wc2, const float* __restrict__ bc2,
    float* __restrict__ out)
{
#if HAS_TCGEN05
    extern __shared__ char smem[];
    const uint32_t sb = smem_u32(smem);
    int*   idxs   = (int*)  (smem + 64);
    float* bc1s   = (float*)(smem + 576);
    float* ba1s   = (float*)(smem + 1088);
    float* ba2s   = (float*)(smem + 3136);
    float* bc2s   = (float*)(smem + 3264);
    float* wc2s   = (float*)(smem + 3328);
    float* polbuf = (float*)(smem + 4352);    // 8192 B
    float* valbuf = (float*)(smem + 12544);   // 2048 B
    float* wa2s   = (float*)(smem + 14592);   // 16384 B -> ends 30976 < 32768

    const int tid = threadIdx.x;
    const int wid = tid >> 5, lid = tid & 31;
    const int sub = wid & 3, jg = wid >> 2;
    const int s   = sub * 32 + lid;
    const int g0  = blockIdx.x * 128;

    if (wid == 0) TC_ALLOC(sb, 512);
    if (tid == 0) { MBAR_INIT(sb + 16, 1); MBAR_INIT(sb + 24, 1); MBAR_INIT(sb + 32, 1); }
    __syncthreads();
    uint32_t tmem;
    asm volatile("ld.shared.b32 %0, [%1];" : "=r"(tmem) : "r"(sb));

    // ---- stage small tables ----
    if (tid < 128) bc1s[tid] = bc1[tid];
#pragma unroll
    for (int i = tid; i < 512; i += 256) ba1s[i] = ba1[i];
    if (tid < 32) ba2s[tid] = ba2[tid];
    if (tid < 2)  bc2s[tid] = bc2[tid];
    if (tid < 256) wc2s[tid] = Wc2[tid];
#pragma unroll
    for (int i = tid; i < 1024; i += 256) ((float4*)wa2s)[i] = ((const float4*)Wa2)[i];

    // ---- build A tiles (x = [xfeat | pref | 0-pad], bf16 hi/lo, swizzled) ----
#pragma unroll
    for (int kt = 0; kt < 2; kt++)
#pragma unroll
        for (int j = 0; j < 4; j++) {
            int u = j * 256 + tid;
            int row = u >> 3, kc8 = u & 7;
            const float* src = g_xfeat + (size_t)(g0 + row) * FEAT + kt * 64 + kc8 * 8;
            float4 a0 = *(const float4*)src, a1 = *(const float4*)(src + 4);
            uint4 H, L;
            split2(a0.x, a0.y, H.x, L.x);
            split2(a0.z, a0.w, H.y, L.y);
            split2(a1.x, a1.y, H.z, L.z);
            split2(a1.z, a1.w, H.w, L.w);
            uint32_t off = (uint32_t)row * 128 + kc8 * 16;
            uint32_t sw  = off ^ ((off >> 3) & 0x70);
            asm volatile("st.shared.v4.b32 [%0], {%1,%2,%3,%4};"
                :: "r"(sb + HA_OFF(kt, 0) + sw), "r"(H.x), "r"(H.y), "r"(H.z), "r"(H.w) : "memory");
            asm volatile("st.shared.v4.b32 [%0], {%1,%2,%3,%4};"
                :: "r"(sb + HA_OFF(kt, 1) + sw), "r"(L.x), "r"(L.y), "r"(L.z), "r"(L.w) : "memory");
        }
#pragma unroll
    for (int j = 0; j < 4; j++) {
        int u = j * 256 + tid;
        int row = u >> 3, kc8 = u & 7;
        if (kc8 != 0) {
            uint32_t off = (uint32_t)row * 128 + kc8 * 16;
            uint32_t sw  = off ^ ((off >> 3) & 0x70);
            asm volatile("st.shared.v4.b32 [%0], {%1,%1,%1,%1};" :: "r"(sb + HA_OFF(2, 0) + sw), "r"(0u) : "memory");
            asm volatile("st.shared.v4.b32 [%0], {%1,%1,%1,%1};" :: "r"(sb + HA_OFF(2, 1) + sw), "r"(0u) : "memory");
        }
    }
    if (tid < 128) {
        int row = tid;
        float p0 = pref[(size_t)(g0 + row) * 2];
        float p1 = pref[(size_t)(g0 + row) * 2 + 1];
        const float PIECE = 0.39269908169872414f;   // pi/2/4
        float theta = atanf(p1 / (p0 + 0.01f));
        int ii = (int)floorf(theta / PIECE);
        idxs[row] = ii < 0 ? 0 : (ii > 3 ? 3 : ii);
        uint32_t h01, l01;
        split2(p0, p1, h01, l01);
        uint32_t off = (uint32_t)row * 128;
        uint32_t sw  = off ^ ((off >> 3) & 0x70);
        asm volatile("st.shared.v4.b32 [%0], {%1,%2,%2,%2};" :: "r"(sb + HA_OFF(2, 0) + sw), "r"(h01), "r"(0u) : "memory");
        asm volatile("st.shared.v4.b32 [%0], {%1,%2,%2,%2};" :: "r"(sb + HA_OFF(2, 1) + sw), "r"(l01), "r"(0u) : "memory");
    }

#define BULK_HB(m)                                                                  \
    do {                                                                            \
        MBAR_EXPECT_TX(sb + 32, 98304u);                                            \
        BULK_G2S(sb + HB_HI(0), (const char*)g_Hsw_hi + (size_t)(m) * 49152, 49152u, sb + 32); \
        BULK_G2S(sb + HB_LO(0), (const char*)g_Hsw_lo + (size_t)(m) * 49152, 49152u, sb + 32); \
    } while (0)

    // 27 dispatches: kt0 kc0-3, kt1 kc0-3, kt2 kc0; 3 split terms each
#define ISSUE_HEAD(dcol, mbar)                                                      \
    do {                                                                            \
        uint32_t en = 0;                                                            \
        _Pragma("unroll")                                                           \
        for (int kt = 0; kt < 3; kt++) {                                            \
            uint64_t ah = make_desc(sb + HA_OFF(kt, 0));                            \
            uint64_t al = make_desc(sb + HA_OFF(kt, 1));                            \
            uint64_t bh = make_desc(sb + HB_HI(kt));                                \
            uint64_t bl = make_desc(sb + HB_LO(kt));                                \
            int nkc = (kt == 2) ? 1 : 4;                                            \
            for (int kc = 0; kc < nkc; kc++) {                                      \
                mma_f16_ss(tmem + (dcol), ah + 2 * kc, bh + 2 * kc, en); en = 1u;   \
                mma_f16_ss(tmem + (dcol), ah + 2 * kc, bl + 2 * kc, 1u);            \
                mma_f16_ss(tmem + (dcol), al + 2 * kc, bh + 2 * kc, 1u);            \
            }                                                                       \
        }                                                                           \
        TC_COMMIT(mbar);                                                            \
    } while (0)

// per-expert epilogue: all 8 warps; thread handles sample s, cols jg*64..+63
#define EXP_EPI(e, cbase)                                                           \
    do {                                                                            \
        float pol[8];                                                               \
        _Pragma("unroll")                                                           \
        for (int a = 0; a < 8; a++) pol[a] = 0.f;                                   \
        _Pragma("unroll")                                                           \
        for (int c = 0; c < 2; c++) {                                               \
            uint32_t r[32];                                                         \
            LDTM_X32(r, tmem + (cbase) + jg * 64 + c * 32);                         \
            TC_WAIT_LD();                                                           \
            _Pragma("unroll")                                                       \
            for (int i = 0; i < 32; i++) {                                          \
                int j = jg * 64 + c * 32 + i;                                       \
                float h = lrelu(__uint_as_float(r[i]) + ba1s[(e) * 128 + j]);       \
                const float* w0 = &wa2s[((e) * 128 + j) * 8];                       \
                _Pragma("unroll")                                                   \
                for (int a = 0; a < 8; a++) pol[a] += h * w0[a];                    \
            }                                                                       \
        }                                                                           \
        if (idxs[s] == (e)) {                                                       \
            _Pragma("unroll")                                                       \
            for (int a = 0; a < 8; a++) polbuf[(s * 2 + jg) * 8 + a] = pol[a];      \
        }                                                                           \
    } while (0)

    __syncthreads();
    // critic: D cols 0..127
    if (wid == 0 && elect_one()) {
        FENCE_ASYNC();
        TC_FENCE_AFTER();
        BULK_HB(0);
        MBAR_WAIT(sb + 32, 0);
        ISSUE_HEAD(0, sb + 16);
    }
    MBAR_WAIT(sb + 16, 0); TC_FENCE_AFTER();            // critic done (all threads)
    // expert 0 -> cols 128..255
    if (wid == 0 && elect_one()) {
        BULK_HB(1);
        MBAR_WAIT(sb + 32, 1);
        ISSUE_HEAD(128, sb + 24);
    }
    // critic epilogue overlaps e0 MMA (reads cols 0..127)
    {
        float v0 = 0.f, v1 = 0.f;
#pragma unroll
        for (int c = 0; c < 2; c++) {
            uint32_t r[32];
            LDTM_X32(r, tmem + jg * 64 + c * 32);
            TC_WAIT_LD();
#pragma unroll
            for (int i = 0; i < 32; i++) {
                int j = jg * 64 + c * 32 + i;
                float h = lrelu(__uint_as_float(r[i]) + bc1s[j]);
                v0 += h * wc2s[j * 2];
                v1 += h * wc2s[j * 2 + 1];
            }
        }
        valbuf[(s * 2 + jg) * 2 + 0] = v0;
        valbuf[(s * 2 + jg) * 2 + 1] = v1;
        TC_FENCE_BEFORE();
    }
    MBAR_WAIT(sb + 24, 0); TC_FENCE_AFTER();            // e0 done
    // expert 1 -> cols 256..383
    if (wid == 0 && elect_one()) {
        BULK_HB(2);
        MBAR_WAIT(sb + 32, 0);
        ISSUE_HEAD(256, sb + 16);
    }
    EXP_EPI(0, 128);                                     // overlaps e1 MMA
    MBAR_WAIT(sb + 16, 1); TC_FENCE_AFTER();            // e1 done
    // expert 2 -> cols 384..511
    if (wid == 0 && elect_one()) {
        BULK_HB(3);
        MBAR_WAIT(sb + 32, 1);
        ISSUE_HEAD(384, sb + 24);
    }
    EXP_EPI(1, 256);                                     // overlaps e2 MMA
    __syncthreads();   // ALL threads past critic epilogue before e3 overwrites cols 0..127
    MBAR_WAIT(sb + 24, 1); TC_FENCE_AFTER();            // e2 done
    // expert 3 -> cols 0..127
    if (wid == 0 && elect_one()) {
        BULK_HB(4);
        MBAR_WAIT(sb + 32, 0);
        ISSUE_HEAD(0, sb + 16);
    }
    EXP_EPI(2, 384);                                     // overlaps e3 MMA
    MBAR_WAIT(sb + 16, 0); TC_FENCE_AFTER();            // e3 done (phase 2, parity 0)
    EXP_EPI(3, 0);
    TC_FENCE_BEFORE();
    __syncthreads();

    // outputs: policy [B,8] then value [B,2]
    for (int i = tid; i < 128 * ACT; i += 256) {
        int r = i >> 3, a = i & 7;
        out[(size_t)(g0 + r) * ACT + a] =
            polbuf[(r * 2 + 0) * 8 + a] + polbuf[(r * 2 + 1) * 8 + a] + ba2s[idxs[r] * 8 + a];
    }
    if (tid < 256) {
        int r = tid >> 1, o = tid & 1;
        out[(size_t)B_ROWS * ACT + (size_t)(g0 + r) * 2 + o] =
            valbuf[(r * 2 + 0) * 2 + o] + valbuf[(r * 2 + 1) * 2 + o] + bc2s[o];
    }
    if (wid == 0) { TC_RELINQ(); TC_DEALLOC(tmem, 512); }

#else
    // ---------------- fallback: proven scalar head ----------------
    extern __shared__ char smem_raw[];
    SmemB* S = (SmemB*)smem_raw;

    const int tid = threadIdx.x;
    const int s = tid & 127;
    const int jh = tid >> 7;
    const int g0 = blockIdx.x * 128;

    for (int i = tid; i < 128 * FEAT; i += 256) {
        int r = i >> 7, c = i & 127;
        S->xs[r][c] = g_xfeat[(size_t)(g0 + r) * FEAT + c];
    }
    if (tid < 128) {
        int r = tid;
        float p0 = pref[(size_t)(g0 + r) * 2];
        float p1 = pref[(size_t)(g0 + r) * 2 + 1];
        S->xs[r][128] = p0;
        S->xs[r][129] = p1;
        const float PIECE = 0.39269908169872414f;
        float theta = atanf(p1 / (p0 + 0.01f));
        int ii = (int)floorf(theta / PIECE);
        S->idxs[r] = ii < 0 ? 0 : (ii > 3 ? 3 : ii);
    }
    {
        const float4* src = (const float4*)Wc1;
        float4* dst = (float4*)S->wbuf;
        for (int i = tid; i < XDIM * FEAT / 4; i += 256) dst[i] = src[i];
    }
    {
        const float4* src = (const float4*)Wa2;
        float4* dst = (float4*)S->wa2s;
        for (int i = tid; i < NEXP * FEAT * ACT / 4; i += 256) dst[i] = src[i];
    }
    for (int i = tid; i < FEAT * 2; i += 256) S->wc2s[i] = Wc2[i];
    if (tid < FEAT) S->bc1s[tid] = bc1[tid];
    for (int i = tid; i < NEXP * FEAT; i += 256) ((float*)S->ba1s)[i] = ba1[i];
    if (tid < NEXP * ACT) ((float*)S->ba2s)[tid] = ba2[tid];
    if (tid < 2) S->bc2s[tid] = bc2[tid];
    __syncthreads();

    unsigned long long acc2[32];

#pragma unroll
    for (int q = 0; q < 32; q++) acc2[q] = 0ULL;
#pragma unroll 2
    for (int k = 0; k < XDIM; k++) {
        unsigned long long x2 = pack2(S->xs[s][k]);
        const ulonglong2* w4 = (const ulonglong2*)(S->wbuf + k * FEAT + jh * 64);
#pragma unroll
        for (int q = 0; q < 16; q++) {
            ulonglong2 w = w4[q];
            FMA2(acc2[2 * q],     x2, w.x);
            FMA2(acc2[2 * q + 1], x2, w.y);
        }
    }
    {
        float v0 = 0.f, v1 = 0.f;
#pragma unroll
        for (int q = 0; q < 32; q++) {
            float2 hp = unpack2(acc2[q]);
            int j0 = jh * 64 + q * 2;
            float h0 = lrelu(hp.x + S->bc1s[j0]);
            float h1 = lrelu(hp.y + S->bc1s[j0 + 1]);
            v0 += h0 * S->wc2s[j0 * 2]     + h1 * S->wc2s[(j0 + 1) * 2];
            v1 += h0 * S->wc2s[j0 * 2 + 1] + h1 * S->wc2s[(j0 + 1) * 2 + 1];
        }
        S->valbuf[s][jh][0] = v0;
        S->valbuf[s][jh][1] = v1;
    }

    for (int e = 0; e < NEXP; e++) {
        __syncthreads();
        {
            const float4* src = (const float4*)(Wa1 + (size_t)e * XDIM * FEAT);
            float4* dst = (float4*)S->wbuf;
            for (int i = tid; i < XDIM * FEAT / 4; i += 256) dst[i] = src[i];
        }
        __syncthreads();
#pragma unroll
        for (int q = 0; q < 32; q++) acc2[q] = 0ULL;
#pragma unroll 2
        for (int k = 0; k < XDIM; k++) {
            unsigned long long x2 = pack2(S->xs[s][k]);
            const ulonglong2* w4 = (const ulonglong2*)(S->wbuf + k * FEAT + jh * 64);
#pragma unroll
            for (int q = 0; q < 16; q++) {
                ulonglong2 w = w4[q];
                FMA2(acc2[2 * q],     x2, w.x);
                FMA2(acc2[2 * q + 1], x2, w.y);
            }
        }
        float pol[ACT];
#pragma unroll
        for (int a = 0; a < ACT; a++) pol[a] = 0.f;
#pragma unroll
        for (int q = 0; q < 32; q++) {
            float2 hp = unpack2(acc2[q]);
            int j0 = jh * 64 + q * 2;
            float h0 = lrelu(hp.x + S->ba1s[e][j0]);
            float h1 = lrelu(hp.y + S->ba1s[e][j0 + 1]);
            const float* w0 = &S->wa2s[(e * FEAT + j0) * ACT];
#pragma unroll
            for (int a = 0; a < ACT; a++) pol[a] += h0 * w0[a] + h1 * w0[ACT + a];
        }
        if (S->idxs[s] == e) {
#pragma unroll
            for (int a = 0; a < ACT; a++) S->polbuf[s][jh][a] = pol[a];
        }
    }
    __syncthreads();

    for (int i = tid; i < 128 * ACT; i += 256) {
        int r = i >> 3, a = i & 7;
        out[(size_t)(g0 + r) * ACT + a] =
            S->polbuf[r][0][a] + S->polbuf[r][1][a] + S->ba2s[S->idxs[r]][a];
    }
    for (int i = tid; i < 128 * 2; i += 256) {
        int r = i >> 1, o = i & 1;
        out[(size_t)B_ROWS * ACT + (size_t)(g0 + r) * 2 + o] =
            S->valbuf[r][0][o] + S->valbuf[r][1][o] + S->bc2s[o];
    }
#endif // HAS_TCGEN05
}

// ============================================================================
extern "C" void kernel_launch(void* const* d_in, const int* in_sizes, int n_in,
                              void* d_out, int out_size)
{
    const float* obs  = (const float*)d_in[0];
    const float* pref = (const float*)d_in[1];
    const float* Wf   = (const float*)d_in[2];
    const float* bf   = (const float*)d_in[3];
    const float* Wa1  = (const float*)d_in[4];
    const float* ba1  = (const float*)d_in[5];
    const float* Wa2  = (const float*)d_in[6];
    const float* ba2  = (const float*)d_in[7];
    const float* Wc1  = (const float*)d_in[8];
    const float* bc1  = (const float*)d_in[9];
    const float* Wc2  = (const float*)d_in[10];
    const float* bc2  = (const float*)d_in[11];
    float* out = (float*)d_out;

    static bool attr_set = false;
    if (!attr_set) {
        cudaFuncSetAttribute(feat_gemm_tc, cudaFuncAttributeMaxDynamicSharedMemorySize, GEMM_SMEM);
        cudaFuncSetAttribute(head_net, cudaFuncAttributeMaxDynamicSharedMemorySize, HEAD_SMEM);
        attr_set = true;
    }

    prep_w<<<(KT_TILES * 1024 + 255) / 256, 256>>>(Wf);
    prep_head<<<(5 * 3 * 1024 + 255) / 256, 256>>>(Wc1, Wa1);
    feat_gemm_tc<<<B_ROWS / 128, 256, GEMM_SMEM>>>(obs, Wf, bf);
    head_net<<<B_ROWS / 128, 256, HEAD_SMEM>>>(
        pref, Wa1, ba1, Wa2, ba2, Wc1, bc1, Wc2, bc2, out);
}

// round 15
// speedup vs baseline: 1.1364x; 1.1364x over previous
#include <cuda_runtime.h>
#include <cuda_bf16.h>
#include <math.h>
#include <stdint.h>

#define B_ROWS 16384
#define K_DIM  10000
#define FEAT   128
#define PREF   2
#define XDIM   130   // FEAT + PREF
#define NEXP   4
#define ACT    8

#define BK       64
#define KT_TILES 157          // ceil(10000/64)

// tcgen05 is an arch-specific ("a") feature. The harness build includes a plain
// compute_103/sm_103 pass where tcgen05 does not exist — that pass gets the
// proven scalar fallback bodies instead. Host pass: value irrelevant.
#if !defined(__CUDA_ARCH__) || defined(__CUDA_ARCH_FEAT_SM103_ALL) || defined(__CUDA_ARCH_FEAT_SM100_ALL) || defined(__CUDA_ARCH_FEAT_SM110_ALL)
#define HAS_TCGEN05 1
#else
#define HAS_TCGEN05 0
#endif

// ---------------- device scratch (no allocations allowed) ----------------
__device__ float g_xfeat[(size_t)B_ROWS * FEAT];
// pre-swizzled bf16 weight tiles (main GEMM): [KT_TILES][128 n x 64 k] 16B units
__device__ uint4 g_Wsw_hi[KT_TILES * 1024];
__device__ uint4 g_Wsw_lo[KT_TILES * 1024];
// pre-swizzled head weights: 5 matrices (0=critic Wc1, 1..4=experts) x 3 ktiles
__device__ uint4 g_Hsw_hi[5 * 3 * 1024];
__device__ uint4 g_Hsw_lo[5 * 3 * 1024];

// ---------------- generic helpers (valid on every target) ----------------
__device__ __forceinline__ float lrelu(float x) { return x >= 0.0f ? x : 0.01f * x; }

// split f32 pair -> bf16x2 hi + bf16x2 lo  (x0 in low half, x1 in high half)
__device__ __forceinline__ void split2(float x0, float x1, uint32_t& h, uint32_t& l) {
    asm("cvt.rn.bf16x2.f32 %0, %1, %2;" : "=r"(h) : "f"(x1), "f"(x0));
    float hf0 = __uint_as_float(h << 16);
    float hf1 = __uint_as_float(h & 0xFFFF0000u);
    float r0 = x0 - hf0, r1 = x1 - hf1;
    asm("cvt.rn.bf16x2.f32 %0, %1, %2;" : "=r"(l) : "f"(r1), "f"(r0));
}

// ---- packed f32x2 helpers (scalar fallback paths) ----
#define FMA2(acc, a, b) asm("fma.rn.f32x2 %0, %1, %2, %0;" : "+l"(acc) : "l"(a), "l"(b))
__device__ __forceinline__ unsigned long long pack2(float v) {
    unsigned long long r; asm("mov.b64 %0, {%1, %1};" : "=l"(r) : "f"(v)); return r;
}
__device__ __forceinline__ float2 unpack2(unsigned long long v) {
    float2 r; asm("mov.b64 {%0, %1}, %2;" : "=f"(r.x), "=f"(r.y) : "l"(v)); return r;
}

// ============================================================================
// Kernel 0: convert Wf [10000 x 128] f32 -> pre-swizzled bf16 hi/lo K-major
// ============================================================================
__global__ __launch_bounds__(256) void prep_w(const float* __restrict__ Wf) {
    int u = blockIdx.x * 256 + threadIdx.x;
    if (u >= KT_TILES * 1024) return;
    int n   = u & 127;
    int kc8 = (u >> 7) & 7;
    int kt  = u >> 10;
    float v[8];
#pragma unroll
    for (int i = 0; i < 8; i++) {
        int k = kt * BK + kc8 * 8 + i;
        v[i] = (k < K_DIM) ? Wf[(size_t)k * FEAT + n] : 0.0f;
    }
    uint4 H, L;
    split2(v[0], v[1], H.x, L.x);
    split2(v[2], v[3], H.y, L.y);
    split2(v[4], v[5], H.z, L.z);
    split2(v[6], v[7], H.w, L.w);
    uint32_t off = n * 128 + kc8 * 16;
    uint32_t sw  = off ^ ((off >> 3) & 0x70);
    int unit = (int)(sw >> 4);
    g_Wsw_hi[kt * 1024 + unit] = H;
    g_Wsw_lo[kt * 1024 + unit] = L;
}

// ============================================================================
// Kernel 0b: head weights -> swizzled bf16 hi/lo B tiles.
// ============================================================================
__global__ __launch_bounds__(256) void prep_head(
    const float* __restrict__ Wc1, const float* __restrict__ Wa1)
{
    int u = blockIdx.x * 256 + threadIdx.x;
    if (u >= 5 * 3 * 1024) return;
    int m    = u / 3072;
    int rem  = u % 3072;
    int kt   = rem >> 10;
    int id   = rem & 1023;
    int j    = id >> 3;
    int kc8  = id & 7;
    float v[8];
#pragma unroll
    for (int i = 0; i < 8; i++) {
        int k = kt * 64 + kc8 * 8 + i;
        float w = 0.0f;
        if (k < XDIM)
            w = (m == 0) ? Wc1[(size_t)k * FEAT + j]
                         : Wa1[(size_t)((m - 1) * XDIM + k) * FEAT + j];
        v[i] = w;
    }
    uint4 H, L;
    split2(v[0], v[1], H.x, L.x);
    split2(v[2], v[3], H.y, L.y);
    split2(v[4], v[5], H.z, L.z);
    split2(v[6], v[7], H.w, L.w);
    uint32_t off = (uint32_t)j * 128 + kc8 * 16;
    uint32_t sw  = off ^ ((off >> 3) & 0x70);
    int unit = (int)(sw >> 4);
    g_Hsw_hi[(m * 3 + kt) * 1024 + unit] = H;
    g_Hsw_lo[(m * 3 + kt) * 1024 + unit] = L;
}

// ============================================================================
// arch-specific helpers (only compiled into the sm_103a/sm_100a device pass)
// ============================================================================
#if HAS_TCGEN05

__device__ __forceinline__ uint32_t smem_u32(const void* p) {
    uint32_t a;
    asm("{ .reg .u64 t; cvta.to.shared.u64 t, %1; cvt.u32.u64 %0, t; }" : "=r"(a) : "l"(p));
    return a;
}
__device__ __forceinline__ uint32_t elect_one() {
    uint32_t p;
    asm volatile("{ .reg .pred p; elect.sync _|p, 0xFFFFFFFF; selp.b32 %0, 1, 0, p; }" : "=r"(p));
    return p;
}
#define MBAR_INIT(a, c) asm volatile("mbarrier.init.shared.b64 [%0], %1;" :: "r"(a), "r"(c) : "memory")
#define MBAR_WAIT(a, ph) do {                                                          \
    asm volatile("{ .reg .pred P;                                                      \
      WL%=: mbarrier.try_wait.parity.acquire.cta.shared::cta.b64 P, [%0], %1, 0x989680;\
      @P bra.uni WD%=; bra.uni WL%=; WD%=: }" :: "r"(a), "r"(ph) : "memory");          \
} while (0)
#define MBAR_EXPECT_TX(a, n) asm volatile("mbarrier.arrive.expect_tx.shared.b64 _, [%0], %1;" :: "r"(a), "r"(n) : "memory")
#define BULK_G2S(dst, src, n, mbar) asm volatile(                                       \
    "cp.async.bulk.shared::cluster.global.mbarrier::complete_tx::bytes [%0], [%1], %2, [%3];" \
    :: "r"(dst), "l"(src), "r"(n), "r"(mbar) : "memory")
#define TC_ALLOC(sa, n)   asm volatile("tcgen05.alloc.cta_group::1.sync.aligned.shared::cta.b32 [%0], %1;" :: "r"(sa), "r"(n) : "memory")
#define TC_DEALLOC(t, n)  asm volatile("tcgen05.dealloc.cta_group::1.sync.aligned.b32 %0, %1;" :: "r"(t), "r"(n))
#define TC_RELINQ()       asm volatile("tcgen05.relinquish_alloc_permit.cta_group::1.sync.aligned;")
#define TC_COMMIT(a)      asm volatile("tcgen05.commit.cta_group::1.mbarrier::arrive::one.shared::cluster.b64 [%0];" :: "r"(a) : "memory")
#define TC_WAIT_LD()      asm volatile("tcgen05.wait::ld.sync.aligned;" ::: "memory")
#define TC_FENCE_AFTER()  asm volatile("tcgen05.fence::after_thread_sync;" ::: "memory")
#define TC_FENCE_BEFORE() asm volatile("tcgen05.fence::before_thread_sync;" ::: "memory")
#define FENCE_ASYNC()     asm volatile("fence.proxy.async.shared::cta;" ::: "memory")

#define LDTM_X32(r, a) asm volatile(                                            \
    "tcgen05.ld.sync.aligned.32x32b.x32.b32 "                                   \
    "{%0,%1,%2,%3,%4,%5,%6,%7,%8,%9,%10,%11,%12,%13,%14,%15,"                   \
    "%16,%17,%18,%19,%20,%21,%22,%23,%24,%25,%26,%27,%28,%29,%30,%31}, [%32];"  \
    : "=r"((r)[0]),"=r"((r)[1]),"=r"((r)[2]),"=r"((r)[3]),                      \
      "=r"((r)[4]),"=r"((r)[5]),"=r"((r)[6]),"=r"((r)[7]),                      \
      "=r"((r)[8]),"=r"((r)[9]),"=r"((r)[10]),"=r"((r)[11]),                    \
      "=r"((r)[12]),"=r"((r)[13]),"=r"((r)[14]),"=r"((r)[15]),                  \
      "=r"((r)[16]),"=r"((r)[17]),"=r"((r)[18]),"=r"((r)[19]),                  \
      "=r"((r)[20]),"=r"((r)[21]),"=r"((r)[22]),"=r"((r)[23]),                  \
      "=r"((r)[24]),"=r"((r)[25]),"=r"((r)[26]),"=r"((r)[27]),                  \
      "=r"((r)[28]),"=r"((r)[29]),"=r"((r)[30]),"=r"((r)[31])                   \
    : "r"(a))

__device__ __forceinline__ uint64_t make_desc(uint32_t addr) {
    const uint64_t BASE = (2ull << 61) | (1ull << 46) | (64ull << 32) | (1ull << 16); // SW128, ver1, SBO=64, LBO=1
    return BASE | ((uint64_t)(addr >> 4) & 0x3FFF);
}

// idesc kind::f16: dtype=F32, a/b=BF16, N=128, M=128
#define MMA_IDESC ((1u << 4) | (1u << 7) | (1u << 10) | (16u << 17) | (8u << 24))

__device__ __forceinline__ void mma_f16_ss(uint32_t d, uint64_t ad, uint64_t bd, uint32_t en) {
    asm volatile(
        "{\n\t.reg .pred p;\n\tsetp.ne.u32 p, %5, 0;\n\t"
        "tcgen05.mma.cta_group::1.kind::f16 [%0], %1, %2, %3, {%4, %4, %4, %4}, p;\n\t}"
        :: "r"(d), "l"(ad), "l"(bd), "r"(MMA_IDESC), "r"(0u), "r"(en) : "memory");
}

#endif // HAS_TCGEN05

// ============================================================================
// Kernel A: x = leaky_relu(obs @ Wf + bf)
//  sm_103a: tcgen05 split-bf16, 3-stage ring, B via cp.async.bulk PREFETCHED
//  two tiles ahead (R13 fetched same-stage and exposed the fill latency).
// smem: [0..4) tmem ptr | 16,24,32 mbarM[3] | 40,48,56 mbarF[3] | tiles @1024
// ============================================================================
#define TILE_OFF(s, b) (1024u + (((uint32_t)(s) * 4u) + (b)) * 16384u)  // 0=Ah 1=Al 2=Bh 3=Bl
#define GEMM_SMEM (1024 + 12 * 16384)

__global__ __launch_bounds__(256) void feat_gemm_tc(
    const float* __restrict__ A,     // obs [B_ROWS, K_DIM]
    const float* __restrict__ W,     // Wf (fallback path only)
    const float* __restrict__ bias)  // bf [FEAT]
{
#if HAS_TCGEN05
    extern __shared__ char smem[];
    const uint32_t sb  = smem_u32(smem);
    const int tid = threadIdx.x;
    const int wid = tid >> 5, lid = tid & 31;
    const int m0  = blockIdx.x * 128;

    if (wid == 0) TC_ALLOC(sb, 128);
    if (tid == 0) {
#pragma unroll
        for (int s = 0; s < 3; s++) { MBAR_INIT(sb + 16 + 8 * s, 1); MBAR_INIT(sb + 40 + 8 * s, 1); }
    }
    __syncthreads();
    uint32_t tmem;
    asm volatile("ld.shared.b32 %0, [%1];" : "=r"(tmem) : "r"(sb));

    float4 areg[8];
    const float4 z4 = make_float4(0.f, 0.f, 0.f, 0.f);

    int rowv[4], col8v[4];
#pragma unroll
    for (int j = 0; j < 4; j++) { int oc = j * 256 + tid; rowv[j] = oc >> 3; col8v[j] = oc & 7; }

#define LOAD_A(kt)                                                                  \
    do {                                                                            \
        _Pragma("unroll")                                                           \
        for (int j = 0; j < 4; j++) {                                               \
            int k = (kt) * BK + col8v[j] * 8;                                       \
            const float* bp = A + (size_t)(m0 + rowv[j]) * K_DIM + k;               \
            areg[2 * j]     = (k + 3 < K_DIM) ? *(const float4*)(bp)     : z4;      \
            areg[2 * j + 1] = (k + 7 < K_DIM) ? *(const float4*)(bp + 4) : z4;      \
        }                                                                           \
    } while (0)

#define STORE_A(s)                                                                  \
    do {                                                                            \
        uint32_t ah_b = sb + TILE_OFF(s, 0), al_b = sb + TILE_OFF(s, 1);            \
        _Pragma("unroll")                                                           \
        for (int j = 0; j < 4; j++) {                                               \
            uint32_t off = rowv[j] * 128 + col8v[j] * 16;                           \
            uint32_t sw  = off ^ ((off >> 3) & 0x70);                               \
            uint4 H, L;                                                             \
            split2(areg[2 * j].x,     areg[2 * j].y,     H.x, L.x);                 \
            split2(areg[2 * j].z,     areg[2 * j].w,     H.y, L.y);                 \
            split2(areg[2 * j + 1].x, areg[2 * j + 1].y, H.z, L.z);                 \
            split2(areg[2 * j + 1].z, areg[2 * j + 1].w, H.w, L.w);                 \
            asm volatile("st.shared.v4.b32 [%0], {%1,%2,%3,%4};"                    \
                :: "r"(ah_b + sw), "r"(H.x), "r"(H.y), "r"(H.z), "r"(H.w) : "memory"); \
            asm volatile("st.shared.v4.b32 [%0], {%1,%2,%3,%4};"                    \
                :: "r"(al_b + sw), "r"(L.x), "r"(L.y), "r"(L.z), "r"(L.w) : "memory"); \
        }                                                                           \
    } while (0)

#define ISSUE_STAGE(s, first)                                                       \
    do {                                                                            \
        uint64_t ahd = make_desc(sb + TILE_OFF(s, 0));                              \
        uint64_t ald = make_desc(sb + TILE_OFF(s, 1));                              \
        uint64_t bhd = make_desc(sb + TILE_OFF(s, 2));                              \
        uint64_t bld = make_desc(sb + TILE_OFF(s, 3));                              \
        uint32_t en = (first) ? 0u : 1u;                                            \
        _Pragma("unroll")                                                           \
        for (int kc = 0; kc < 4; kc++) {                                            \
            mma_f16_ss(tmem, ahd + 2 * kc, bhd + 2 * kc, en); en = 1u;              \
            mma_f16_ss(tmem, ahd + 2 * kc, bld + 2 * kc, 1u);                       \
            mma_f16_ss(tmem, ald + 2 * kc, bhd + 2 * kc, 1u);                       \
        }                                                                           \
    } while (0)

#define BULK_B(kt, s)                                                               \
    do {                                                                            \
        uint32_t mf = sb + 40 + 8u * (s);                                           \
        MBAR_EXPECT_TX(mf, 32768u);                                                 \
        BULK_G2S(sb + TILE_OFF(s, 2), (const char*)g_Wsw_hi + (size_t)(kt) * 16384, 16384u, mf); \
        BULK_G2S(sb + TILE_OFF(s, 3), (const char*)g_Wsw_lo + (size_t)(kt) * 16384, 16384u, mf); \
    } while (0)

    LOAD_A(0);
    // prologue: seed B fills for tiles 0 and 1 (buffers 0, 1)
    if (wid == 0 && elect_one()) {
        BULK_B(0, 0);
        BULK_B(1, 1);
    }

#pragma unroll 1
    for (int kt = 0; kt < KT_TILES; kt++) {
        const int s = kt % 3, c = kt / 3;
        const uint32_t mbM = sb + 16 + 8u * s;
        if (kt >= 3) { MBAR_WAIT(mbM, (c - 1) & 1); TC_FENCE_AFTER(); }
        STORE_A(s);
        if (kt + 1 < KT_TILES) LOAD_A(kt + 1);
        __syncthreads();
        if (wid == 0 && elect_one()) {
            FENCE_ASYNC();
            TC_FENCE_AFTER();
            MBAR_WAIT(sb + 40 + 8u * s, c & 1);   // B fill for tile kt (2 iters in flight)
            ISSUE_STAGE(s, kt == 0);
            TC_COMMIT(mbM);
            // prefetch B for tile kt+2 into buffer (kt+2)%3; safe once that
            // buffer's previous MMAs (tile kt-1) have drained — they precede
            // tile kt's just-committed MMAs in queue order.
            if (kt + 2 < KT_TILES) {
                const int s2 = (kt + 2) % 3, c2 = (kt + 2) / 3;
                if (kt + 2 >= 3) MBAR_WAIT(sb + 16 + 8u * s2, (c2 - 1) & 1);
                BULK_B(kt + 2, s2);
            }
        }
    }

    // last commit (kt=156) went to mbarM[0]; commit #52 -> parity 0
    MBAR_WAIT(sb + 16, 0);
    TC_FENCE_AFTER();

    {
        const int sub = wid & 3;
        const int mrow = m0 + sub * 32 + lid;
        const int cb = (wid >> 2) * 64;
        float* orow = g_xfeat + (size_t)mrow * FEAT + cb;
#pragma unroll
        for (int half = 0; half < 2; half++) {
            uint32_t r[32];
            LDTM_X32(r, tmem + cb + half * 32);
            TC_WAIT_LD();
#pragma unroll
            for (int q = 0; q < 8; q++) {
                float4 bq = *(const float4*)(bias + cb + half * 32 + q * 4);
                float4 o;
                o.x = lrelu(__uint_as_float(r[q * 4 + 0]) + bq.x);
                o.y = lrelu(__uint_as_float(r[q * 4 + 1]) + bq.y);
                o.z = lrelu(__uint_as_float(r[q * 4 + 2]) + bq.z);
                o.w = lrelu(__uint_as_float(r[q * 4 + 3]) + bq.w);
                *(float4*)(orow + half * 32 + q * 4) = o;
            }
        }
    }
    TC_FENCE_BEFORE();
    __syncthreads();
    if (wid == 0) { TC_RELINQ(); TC_DEALLOC(tmem, 128); }

#else
    // ---------------- fallback: proven scalar f32x2 GEMM ----------------
    __shared__ float As[32][132];
    __shared__ float Bs[32][128];

    const int tid = threadIdx.x;
    const int tx = tid & 15;
    const int ty = tid >> 4;
    const int m0 = blockIdx.x * 128;

    unsigned long long acc[8][4];
#pragma unroll
    for (int i = 0; i < 8; i++)
#pragma unroll
        for (int j = 0; j < 4; j++) acc[i][j] = 0ULL;

    const float4 z4 = make_float4(0.f, 0.f, 0.f, 0.f);
    float4 aReg[4], bReg[4];
    const int KT = (K_DIM + 31) / 32;

    {
        const int k0 = 0;
#pragma unroll
        for (int j = 0; j < 4; j++) {
            int c = tid + 256 * j;
            int row = c >> 3, kq = c & 7;
            int k = k0 + kq * 4;
            aReg[j] = (k < K_DIM)
                ? *(const float4*)(A + (size_t)(m0 + row) * K_DIM + k) : z4;
        }
#pragma unroll
        for (int j = 0; j < 4; j++) {
            int c = tid + 256 * j;
            int kr = c >> 5, nq = c & 31;
            int k = k0 + kr;
            bReg[j] = (k < K_DIM)
                ? *(const float4*)(W + (size_t)k * FEAT + nq * 4) : z4;
        }
    }

#pragma unroll 1
    for (int kt = 0; kt < KT; kt++) {
        __syncthreads();
#pragma unroll
        for (int j = 0; j < 4; j++) {
            int c = tid + 256 * j;
            int row = c >> 3, kq = c & 7;
            As[kq * 4 + 0][row] = aReg[j].x;
            As[kq * 4 + 1][row] = aReg[j].y;
            As[kq * 4 + 2][row] = aReg[j].z;
            As[kq * 4 + 3][row] = aReg[j].w;
        }
#pragma unroll
        for (int j = 0; j < 4; j++) {
            int c = tid + 256 * j;
            int kr = c >> 5, nq = c & 31;
            *(float4*)&Bs[kr][nq * 4] = bReg[j];
        }
        __syncthreads();

        if (kt + 1 < KT) {
            const int k0 = (kt + 1) * 32;
#pragma unroll
            for (int j = 0; j < 4; j++) {
                int c = tid + 256 * j;
                int row = c >> 3, kq = c & 7;
                int k = k0 + kq * 4;
                aReg[j] = (k < K_DIM)
                    ? *(const float4*)(A + (size_t)(m0 + row) * K_DIM + k) : z4;
            }
#pragma unroll
            for (int j = 0; j < 4; j++) {
                int c = tid + 256 * j;
                int kr = c >> 5, nq = c & 31;
                int k = k0 + kr;
                bReg[j] = (k < K_DIM)
                    ? *(const float4*)(W + (size_t)k * FEAT + nq * 4) : z4;
            }
        }

#pragma unroll 8
        for (int k = 0; k < 32; k++) {
            float4 a0 = *(const float4*)&As[k][ty * 8];
            float4 a1 = *(const float4*)&As[k][ty * 8 + 4];
            ulonglong2 b0 = *(const ulonglong2*)&Bs[k][tx * 8];
            ulonglong2 b1 = *(const ulonglong2*)&Bs[k][tx * 8 + 4];
            float av[8] = {a0.x, a0.y, a0.z, a0.w, a1.x, a1.y, a1.z, a1.w};
#pragma unroll
            for (int im = 0; im < 8; im++) {
                unsigned long long a2 = pack2(av[im]);
                FMA2(acc[im][0], a2, b0.x);
                FMA2(acc[im][1], a2, b0.y);
                FMA2(acc[im][2], a2, b1.x);
                FMA2(acc[im][3], a2, b1.y);
            }
        }
    }

    const int n0 = tx * 8;
#pragma unroll
    for (int im = 0; im < 8; im++) {
        size_t m = (size_t)m0 + ty * 8 + im;
#pragma unroll
        for (int jp = 0; jp < 4; jp++) {
            float2 v = unpack2(acc[im][jp]);
            int n = n0 + jp * 2;
            v.x = lrelu(v.x + bias[n]);
            v.y = lrelu(v.y + bias[n + 1]);
            *(float2*)&g_xfeat[m * FEAT + n] = v;
        }
    }
#endif // HAS_TCGEN05
}

// ============================================================================
// Kernel B: routing + MoE actor + critic (unchanged from R13 — 27.4 us).
// smem (tc path):
//  0 tmem ptr | 16 mbar0 | 24 mbar1 | 32 mbarBF | 64 idxs[128] | 576 bc1s[128]
//  1088 ba1s[4][128] | 3136 ba2s[4][8] | 3264 bc2s[2] | 3328 wc2s[256]
//  4352 polbuf[128][2][8] (8192B) | 12544 valbuf[128][2][2] (2048B)
//  14592 wa2s[4096] (16384B, ends 30976)
//  32768 A tiles (3kt x hi/lo x 16KB) | 131072 B hi (3x16KB) | 180224 B lo (3x16KB)
// ============================================================================
#define HA_OFF(kt, h) (32768u  + ((uint32_t)(kt) * 2u + (h)) * 16384u)
#define HB_HI(kt)     (131072u + (uint32_t)(kt) * 16384u)
#define HB_LO(kt)     (180224u + (uint32_t)(kt) * 16384u)
#define HEAD_SMEM 229376

struct SmemB {
    float xs[128][133];
    float wbuf[XDIM * FEAT];
    float wa2s[NEXP * FEAT * ACT];
    float wc2s[FEAT * 2];
    float polbuf[128][2][ACT];
    float valbuf[128][2][2];
    float bc1s[FEAT];
    float ba1s[NEXP][FEAT];
    float ba2s[NEXP][ACT];
    float bc2s[2];
    int   idxs[128];
};

__global__ __launch_bounds__(256) void head_net(
    const float* __restrict__ pref,
    const float* __restrict__ Wa1, const float* __restrict__ ba1,
    const float* __restrict__ Wa2, const float* __restrict__ ba2,
    const float* __restrict__ Wc1, const float* __restrict__ bc1,
    const float* __restrict__ Wc2, const float* __restrict__ bc2,
    float* __restrict__ out)
{
#if HAS_TCGEN05
    extern __shared__ char smem[];
    const uint32_t sb = smem_u32(smem);
    int*   idxs   = (int*)  (smem + 64);
    float* bc1s   = (float*)(smem + 576);
    float* ba1s   = (float*)(smem + 1088);
    float* ba2s   = (float*)(smem + 3136);
    float* bc2s   = (float*)(smem + 3264);
    float* wc2s   = (float*)(smem + 3328);
    float* polbuf = (float*)(smem + 4352);    // 8192 B
    float* valbuf = (float*)(smem + 12544);   // 2048 B
    float* wa2s   = (float*)(smem + 14592);   // 16384 B -> ends 30976 < 32768

    const int tid = threadIdx.x;
    const int wid = tid >> 5, lid = tid & 31;
    const int sub = wid & 3, jg = wid >> 2;
    const int s   = sub * 32 + lid;
    const int g0  = blockIdx.x * 128;

    if (wid == 0) TC_ALLOC(sb, 512);
    if (tid == 0) { MBAR_INIT(sb + 16, 1); MBAR_INIT(sb + 24, 1); MBAR_INIT(sb + 32, 1); }
    __syncthreads();
    uint32_t tmem;
    asm volatile("ld.shared.b32 %0, [%1];" : "=r"(tmem) : "r"(sb));

    // ---- stage small tables ----
    if (tid < 128) bc1s[tid] = bc1[tid];
#pragma unroll
    for (int i = tid; i < 512; i += 256) ba1s[i] = ba1[i];
    if (tid < 32) ba2s[tid] = ba2[tid];
    if (tid < 2)  bc2s[tid] = bc2[tid];
    if (tid < 256) wc2s[tid] = Wc2[tid];
#pragma unroll
    for (int i = tid; i < 1024; i += 256) ((float4*)wa2s)[i] = ((const float4*)Wa2)[i];

    // ---- build A tiles (x = [xfeat | pref | 0-pad], bf16 hi/lo, swizzled) ----
#pragma unroll
    for (int kt = 0; kt < 2; kt++)
#pragma unroll
        for (int j = 0; j < 4; j++) {
            int u = j * 256 + tid;
            int row = u >> 3, kc8 = u & 7;
            const float* src = g_xfeat + (size_t)(g0 + row) * FEAT + kt * 64 + kc8 * 8;
            float4 a0 = *(const float4*)src, a1 = *(const float4*)(src + 4);
            uint4 H, L;
            split2(a0.x, a0.y, H.x, L.x);
            split2(a0.z, a0.w, H.y, L.y);
            split2(a1.x, a1.y, H.z, L.z);
            split2(a1.z, a1.w, H.w, L.w);
            uint32_t off = (uint32_t)row * 128 + kc8 * 16;
            uint32_t sw  = off ^ ((off >> 3) & 0x70);
            asm volatile("st.shared.v4.b32 [%0], {%1,%2,%3,%4};"
                :: "r"(sb + HA_OFF(kt, 0) + sw), "r"(H.x), "r"(H.y), "r"(H.z), "r"(H.w) : "memory");
            asm volatile("st.shared.v4.b32 [%0], {%1,%2,%3,%4};"
                :: "r"(sb + HA_OFF(kt, 1) + sw), "r"(L.x), "r"(L.y), "r"(L.z), "r"(L.w) : "memory");
        }
#pragma unroll
    for (int j = 0; j < 4; j++) {
        int u = j * 256 + tid;
        int row = u >> 3, kc8 = u & 7;
        if (kc8 != 0) {
            uint32_t off = (uint32_t)row * 128 + kc8 * 16;
            uint32_t sw  = off ^ ((off >> 3) & 0x70);
            asm volatile("st.shared.v4.b32 [%0], {%1,%1,%1,%1};" :: "r"(sb + HA_OFF(2, 0) + sw), "r"(0u) : "memory");
            asm volatile("st.shared.v4.b32 [%0], {%1,%1,%1,%1};" :: "r"(sb + HA_OFF(2, 1) + sw), "r"(0u) : "memory");
        }
    }
    if (tid < 128) {
        int row = tid;
        float p0 = pref[(size_t)(g0 + row) * 2];
        float p1 = pref[(size_t)(g0 + row) * 2 + 1];
        const float PIECE = 0.39269908169872414f;   // pi/2/4
        float theta = atanf(p1 / (p0 + 0.01f));
        int ii = (int)floorf(theta / PIECE);
        idxs[row] = ii < 0 ? 0 : (ii > 3 ? 3 : ii);
        uint32_t h01, l01;
        split2(p0, p1, h01, l01);
        uint32_t off = (uint32_t)row * 128;
        uint32_t sw  = off ^ ((off >> 3) & 0x70);
        asm volatile("st.shared.v4.b32 [%0], {%1,%2,%2,%2};" :: "r"(sb + HA_OFF(2, 0) + sw), "r"(h01), "r"(0u) : "memory");
        asm volatile("st.shared.v4.b32 [%0], {%1,%2,%2,%2};" :: "r"(sb + HA_OFF(2, 1) + sw), "r"(l01), "r"(0u) : "memory");
    }

#define BULK_HB(m)                                                                  \
    do {                                                                            \
        MBAR_EXPECT_TX(sb + 32, 98304u);                                            \
        BULK_G2S(sb + HB_HI(0), (const char*)g_Hsw_hi + (size_t)(m) * 49152, 49152u, sb + 32); \
        BULK_G2S(sb + HB_LO(0), (const char*)g_Hsw_lo + (size_t)(m) * 49152, 49152u, sb + 32); \
    } while (0)

    // 27 dispatches: kt0 kc0-3, kt1 kc0-3, kt2 kc0; 3 split terms each
#define ISSUE_HEAD(dcol, mbar)                                                      \
    do {                                                                            \
        uint32_t en = 0;                                                            \
        _Pragma("unroll")                                                           \
        for (int kt = 0; kt < 3; kt++) {                                            \
            uint64_t ah = make_desc(sb + HA_OFF(kt, 0));                            \
            uint64_t al = make_desc(sb + HA_OFF(kt, 1));                            \
            uint64_t bh = make_desc(sb + HB_HI(kt));                                \
            uint64_t bl = make_desc(sb + HB_LO(kt));                                \
            int nkc = (kt == 2) ? 1 : 4;                                            \
            for (int kc = 0; kc < nkc; kc++) {                                      \
                mma_f16_ss(tmem + (dcol), ah + 2 * kc, bh + 2 * kc, en); en = 1u;   \
                mma_f16_ss(tmem + (dcol), ah + 2 * kc, bl + 2 * kc, 1u);            \
                mma_f16_ss(tmem + (dcol), al + 2 * kc, bh + 2 * kc, 1u);            \
            }                                                                       \
        }                                                                           \
        TC_COMMIT(mbar);                                                            \
    } while (0)

// per-expert epilogue: all 8 warps; thread handles sample s, cols jg*64..+63
#define EXP_EPI(e, cbase)                                                           \
    do {                                                                            \
        float pol[8];                                                               \
        _Pragma("unroll")                                                           \
        for (int a = 0; a < 8; a++) pol[a] = 0.f;                                   \
        _Pragma("unroll")                                                           \
        for (int c = 0; c < 2; c++) {                                               \
            uint32_t r[32];                                                         \
            LDTM_X32(r, tmem + (cbase) + jg * 64 + c * 32);                         \
            TC_WAIT_LD();                                                           \
            _Pragma("unroll")                                                       \
            for (int i = 0; i < 32; i++) {                                          \
                int j = jg * 64 + c * 32 + i;                                       \
                float h = lrelu(__uint_as_float(r[i]) + ba1s[(e) * 128 + j]);       \
                const float* w0 = &wa2s[((e) * 128 + j) * 8];                       \
                _Pragma("unroll")                                                   \
                for (int a = 0; a < 8; a++) pol[a] += h * w0[a];                    \
            }                                                                       \
        }                                                                           \
        if (idxs[s] == (e)) {                                                       \
            _Pragma("unroll")                                                       \
            for (int a = 0; a < 8; a++) polbuf[(s * 2 + jg) * 8 + a] = pol[a];      \
        }                                                                           \
    } while (0)

    __syncthreads();
    // critic: D cols 0..127
    if (wid == 0 && elect_one()) {
        FENCE_ASYNC();
        TC_FENCE_AFTER();
        BULK_HB(0);
        MBAR_WAIT(sb + 32, 0);
        ISSUE_HEAD(0, sb + 16);
    }
    MBAR_WAIT(sb + 16, 0); TC_FENCE_AFTER();            // critic done (all threads)
    // expert 0 -> cols 128..255
    if (wid == 0 && elect_one()) {
        BULK_HB(1);
        MBAR_WAIT(sb + 32, 1);
        ISSUE_HEAD(128, sb + 24);
    }
    // critic epilogue overlaps e0 MMA (reads cols 0..127)
    {
        float v0 = 0.f, v1 = 0.f;
#pragma unroll
        for (int c = 0; c < 2; c++) {
            uint32_t r[32];
            LDTM_X32(r, tmem + jg * 64 + c * 32);
            TC_WAIT_LD();
#pragma unroll
            for (int i = 0; i < 32; i++) {
                int j = jg * 64 + c * 32 + i;
                float h = lrelu(__uint_as_float(r[i]) + bc1s[j]);
                v0 += h * wc2s[j * 2];
                v1 += h * wc2s[j * 2 + 1];
            }
        }
        valbuf[(s * 2 + jg) * 2 + 0] = v0;
        valbuf[(s * 2 + jg) * 2 + 1] = v1;
        TC_FENCE_BEFORE();
    }
    MBAR_WAIT(sb + 24, 0); TC_FENCE_AFTER();            // e0 done
    // expert 1 -> cols 256..383
    if (wid == 0 && elect_one()) {
        BULK_HB(2);
        MBAR_WAIT(sb + 32, 0);
        ISSUE_HEAD(256, sb + 16);
    }
    EXP_EPI(0, 128);                                     // overlaps e1 MMA
    MBAR_WAIT(sb + 16, 1); TC_FENCE_AFTER();            // e1 done
    // expert 2 -> cols 384..511
    if (wid == 0 && elect_one()) {
        BULK_HB(3);
        MBAR_WAIT(sb + 32, 1);
        ISSUE_HEAD(384, sb + 24);
    }
    EXP_EPI(1, 256);                                     // overlaps e2 MMA
    __syncthreads();   // ALL threads past critic epilogue before e3 overwrites cols 0..127
    MBAR_WAIT(sb + 24, 1); TC_FENCE_AFTER();            // e2 done
    // expert 3 -> cols 0..127
    if (wid == 0 && elect_one()) {
        BULK_HB(4);
        MBAR_WAIT(sb + 32, 0);
        ISSUE_HEAD(0, sb + 16);
    }
    EXP_EPI(2, 384);                                     // overlaps e3 MMA
    MBAR_WAIT(sb + 16, 0); TC_FENCE_AFTER();            // e3 done (phase 2, parity 0)
    EXP_EPI(3, 0);
    TC_FENCE_BEFORE();
    __syncthreads();

    // outputs: policy [B,8] then value [B,2]
    for (int i = tid; i < 128 * ACT; i += 256) {
        int r = i >> 3, a = i & 7;
        out[(size_t)(g0 + r) * ACT + a] =
            polbuf[(r * 2 + 0) * 8 + a] + polbuf[(r * 2 + 1) * 8 + a] + ba2s[idxs[r] * 8 + a];
    }
    if (tid < 256) {
        int r = tid >> 1, o = tid & 1;
        out[(size_t)B_ROWS * ACT + (size_t)(g0 + r) * 2 + o] =
            valbuf[(r * 2 + 0) * 2 + o] + valbuf[(r * 2 + 1) * 2 + o] + bc2s[o];
    }
    if (wid == 0) { TC_RELINQ(); TC_DEALLOC(tmem, 512); }

#else
    // ---------------- fallback: proven scalar head ----------------
    extern __shared__ char smem_raw[];
    SmemB* S = (SmemB*)smem_raw;

    const int tid = threadIdx.x;
    const int s = tid & 127;
    const int jh = tid >> 7;
    const int g0 = blockIdx.x * 128;

    for (int i = tid; i < 128 * FEAT; i += 256) {
        int r = i >> 7, c = i & 127;
        S->xs[r][c] = g_xfeat[(size_t)(g0 + r) * FEAT + c];
    }
    if (tid < 128) {
        int r = tid;
        float p0 = pref[(size_t)(g0 + r) * 2];
        float p1 = pref[(size_t)(g0 + r) * 2 + 1];
        S->xs[r][128] = p0;
        S->xs[r][129] = p1;
        const float PIECE = 0.39269908169872414f;
        float theta = atanf(p1 / (p0 + 0.01f));
        int ii = (int)floorf(theta / PIECE);
        S->idxs[r] = ii < 0 ? 0 : (ii > 3 ? 3 : ii);
    }
    {
        const float4* src = (const float4*)Wc1;
        float4* dst = (float4*)S->wbuf;
        for (int i = tid; i < XDIM * FEAT / 4; i += 256) dst[i] = src[i];
    }
    {
        const float4* src = (const float4*)Wa2;
        float4* dst = (float4*)S->wa2s;
        for (int i = tid; i < NEXP * FEAT * ACT / 4; i += 256) dst[i] = src[i];
    }
    for (int i = tid; i < FEAT * 2; i += 256) S->wc2s[i] = Wc2[i];
    if (tid < FEAT) S->bc1s[tid] = bc1[tid];
    for (int i = tid; i < NEXP * FEAT; i += 256) ((float*)S->ba1s)[i] = ba1[i];
    if (tid < NEXP * ACT) ((float*)S->ba2s)[tid] = ba2[tid];
    if (tid < 2) S->bc2s[tid] = bc2[tid];
    __syncthreads();

    unsigned long long acc2[32];

#pragma unroll
    for (int q = 0; q < 32; q++) acc2[q] = 0ULL;
#pragma unroll 2
    for (int k = 0; k < XDIM; k++) {
        unsigned long long x2 = pack2(S->xs[s][k]);
        const ulonglong2* w4 = (const ulonglong2*)(S->wbuf + k * FEAT + jh * 64);
#pragma unroll
        for (int q = 0; q < 16; q++) {
            ulonglong2 w = w4[q];
            FMA2(acc2[2 * q],     x2, w.x);
            FMA2(acc2[2 * q + 1], x2, w.y);
        }
    }
    {
        float v0 = 0.f, v1 = 0.f;
#pragma unroll
        for (int q = 0; q < 32; q++) {
            float2 hp = unpack2(acc2[q]);
            int j0 = jh * 64 + q * 2;
            float h0 = lrelu(hp.x + S->bc1s[j0]);
            float h1 = lrelu(hp.y + S->bc1s[j0 + 1]);
            v0 += h0 * S->wc2s[j0 * 2]     + h1 * S->wc2s[(j0 + 1) * 2];
            v1 += h0 * S->wc2s[j0 * 2 + 1] + h1 * S->wc2s[(j0 + 1) * 2 + 1];
        }
        S->valbuf[s][jh][0] = v0;
        S->valbuf[s][jh][1] = v1;
    }

    for (int e = 0; e < NEXP; e++) {
        __syncthreads();
        {
            const float4* src = (const float4*)(Wa1 + (size_t)e * XDIM * FEAT);
            float4* dst = (float4*)S->wbuf;
            for (int i = tid; i < XDIM * FEAT / 4; i += 256) dst[i] = src[i];
        }
        __syncthreads();
#pragma unroll
        for (int q = 0; q < 32; q++) acc2[q] = 0ULL;
#pragma unroll 2
        for (int k = 0; k < XDIM; k++) {
            unsigned long long x2 = pack2(S->xs[s][k]);
            const ulonglong2* w4 = (const ulonglong2*)(S->wbuf + k * FEAT + jh * 64);
#pragma unroll
            for (int q = 0; q < 16; q++) {
                ulonglong2 w = w4[q];
                FMA2(acc2[2 * q],     x2, w.x);
                FMA2(acc2[2 * q + 1], x2, w.y);
            }
        }
        float pol[ACT];
#pragma unroll
        for (int a = 0; a < ACT; a++) pol[a] = 0.f;
#pragma unroll
        for (int q = 0; q < 32; q++) {
            float2 hp = unpack2(acc2[q]);
            int j0 = jh * 64 + q * 2;
            float h0 = lrelu(hp.x + S->ba1s[e][j0]);
            float h1 = lrelu(hp.y + S->ba1s[e][j0 + 1]);
            const float* w0 = &S->wa2s[(e * FEAT + j0) * ACT];
#pragma unroll
            for (int a = 0; a < ACT; a++) pol[a] += h0 * w0[a] + h1 * w0[ACT + a];
        }
        if (S->idxs[s] == e) {
#pragma unroll
            for (int a = 0; a < ACT; a++) S->polbuf[s][jh][a] = pol[a];
        }
    }
    __syncthreads();

    for (int i = tid; i < 128 * ACT; i += 256) {
        int r = i >> 3, a = i & 7;
        out[(size_t)(g0 + r) * ACT + a] =
            S->polbuf[r][0][a] + S->polbuf[r][1][a] + S->ba2s[S->idxs[r]][a];
    }
    for (int i = tid; i < 128 * 2; i += 256) {
        int r = i >> 1, o = i & 1;
        out[(size_t)B_ROWS * ACT + (size_t)(g0 + r) * 2 + o] =
            S->valbuf[r][0][o] + S->valbuf[r][1][o] + S->bc2s[o];
    }
#endif // HAS_TCGEN05
}

// ============================================================================
extern "C" void kernel_launch(void* const* d_in, const int* in_sizes, int n_in,
                              void* d_out, int out_size)
{
    const float* obs  = (const float*)d_in[0];
    const float* pref = (const float*)d_in[1];
    const float* Wf   = (const float*)d_in[2];
    const float* bf   = (const float*)d_in[3];
    const float* Wa1  = (const float*)d_in[4];
    const float* ba1  = (const float*)d_in[5];
    const float* Wa2  = (const float*)d_in[6];
    const float* ba2  = (const float*)d_in[7];
    const float* Wc1  = (const float*)d_in[8];
    const float* bc1  = (const float*)d_in[9];
    const float* Wc2  = (const float*)d_in[10];
    const float* bc2  = (const float*)d_in[11];
    float* out = (float*)d_out;

    static bool attr_set = false;
    if (!attr_set) {
        cudaFuncSetAttribute(feat_gemm_tc, cudaFuncAttributeMaxDynamicSharedMemorySize, GEMM_SMEM);
        cudaFuncSetAttribute(head_net, cudaFuncAttributeMaxDynamicSharedMemorySize, HEAD_SMEM);
        attr_set = true;
    }

    prep_w<<<(KT_TILES * 1024 + 255) / 256, 256>>>(Wf);
    prep_head<<<(5 * 3 * 1024 + 255) / 256, 256>>>(Wc1, Wa1);
    feat_gemm_tc<<<B_ROWS / 128, 256, GEMM_SMEM>>>(obs, Wf, bf);
    head_net<<<B_ROWS / 128, 256, HEAD_SMEM>>>(
        pref, Wa1, ba1, Wa2, ba2, Wc1, bc1, Wc2, bc2, out);
}